// round 6
// baseline (speedup 1.0000x reference)
#include <cuda_runtime.h>
#include <cstdint>
#include <cstddef>

#define SEQ   512
#define BATCH 64
#define INDIM 512
#define HID   1024
#define NCTA  128

#define TILE_F   (64 * 68)          // floats per padded k-tile (64 rows x 68)
#define TILE_B   (TILE_F * 4)       // 17408 bytes
#define NTILE    16                 // 16 k-tiles of 64 cover K=1024
#define HT_BUF_F ((size_t)NTILE * TILE_F)

// ---------------- device scratch ----------------
__device__ float g_xproj[(size_t)SEQ * 3 * BATCH * HID];   // [s][gate][b][j]
__device__ float g_h[BATCH * HID];                 // exact fp32 hidden (linear)
__device__ float g_ht_t[2 * HT_BUF_F];             // tf32 hidden, tiled, double-buffered
__device__ float g_rh_t[HT_BUF_F];                 // tf32 r*h, tiled
__device__ float g_z[BATCH * HID];
__device__ unsigned g_cnt_rh[NTILE];               // rh tile producer counters (4/tile/step)
__device__ unsigned g_cnt_ht[NTILE];               // ht tile producer counters (8/tile/step)
__device__ unsigned g_flag_z[64];                  // z-CTA publish flags (=s+1)

// ---------------- helpers ----------------
__device__ __forceinline__ float to_tf32(float x) {
    uint32_t u;
    asm("cvt.rna.tf32.f32 %0, %1;" : "=r"(u) : "f"(x));
    return __uint_as_float(u);
}

__device__ __forceinline__ void mma_tf32(float c[4], const float a[4], const float b[2]) {
    asm volatile(
        "mma.sync.aligned.m16n8k8.row.col.f32.tf32.tf32.f32 "
        "{%0,%1,%2,%3}, {%4,%5,%6,%7}, {%8,%9}, {%0,%1,%2,%3};\n"
        : "+f"(c[0]), "+f"(c[1]), "+f"(c[2]), "+f"(c[3])
        : "r"(__float_as_uint(a[0])), "r"(__float_as_uint(a[1])),
          "r"(__float_as_uint(a[2])), "r"(__float_as_uint(a[3])),
          "r"(__float_as_uint(b[0])), "r"(__float_as_uint(b[1])));
}

__device__ __forceinline__ float sigmoidf_(float x) {
    return 1.0f / (1.0f + __expf(-x));
}

__device__ __forceinline__ void mbar_init(unsigned addr, unsigned cnt) {
    asm volatile("mbarrier.init.shared.b64 [%0], %1;" :: "r"(addr), "r"(cnt) : "memory");
}
__device__ __forceinline__ void mbar_expect_tx(unsigned addr, unsigned tx) {
    asm volatile("mbarrier.arrive.expect_tx.shared.b64 _, [%0], %1;"
                 :: "r"(addr), "r"(tx) : "memory");
}
__device__ __forceinline__ void mbar_wait(unsigned addr, unsigned parity) {
    asm volatile(
        "{\n\t.reg .pred P;\n\t"
        "LW%=:\n\t"
        "mbarrier.try_wait.parity.shared.b64 P, [%0], %1;\n\t"
        "@P bra.uni LD%=;\n\t"
        "bra.uni LW%=;\n\t"
        "LD%=:\n\t}"
        :: "r"(addr), "r"(parity) : "memory");
}
__device__ __forceinline__ void bulk_cp(float* dst_smem, const float* src,
                                        unsigned bytes, unsigned mbar) {
    unsigned d = (unsigned)__cvta_generic_to_shared(dst_smem);
    asm volatile(
        "cp.async.bulk.shared::cta.global.mbarrier::complete_tx::bytes [%0], [%1], %2, [%3];"
        :: "r"(d), "l"(src), "r"(bytes), "r"(mbar) : "memory");
}

__device__ __forceinline__ unsigned ld_acq(const unsigned* p) {
    unsigned v;
    asm volatile("ld.acquire.gpu.global.u32 %0, [%1];" : "=r"(v) : "l"(p) : "memory");
    return v;
}
__device__ __forceinline__ void red_rel(unsigned* p, unsigned v) {
    asm volatile("red.release.gpu.global.add.u32 [%0], %1;" :: "l"(p), "r"(v) : "memory");
}
__device__ __forceinline__ void st_rel(unsigned* p, unsigned v) {
    asm volatile("st.release.gpu.global.u32 [%0], %1;" :: "l"(p), "r"(v) : "memory");
}

// ---------------- init: h, ht buf0, counters ----------------
__global__ void init_kernel(const float* __restrict__ init_h) {
    int i = blockIdx.x * blockDim.x + threadIdx.x;
    if (i < NTILE) { g_cnt_rh[i] = 0u; g_cnt_ht[i] = 0u; }
    if (i < 64) g_flag_z[i] = 0u;
    if (i < BATCH * HID) {
        int b = i >> 10, j = i & 1023;
        float v = init_h[i];
        g_h[i] = v;
        g_ht_t[(size_t)(j >> 6) * TILE_F + b * 68 + (j & 63)] = to_tf32(v);
    }
}

// ---------------- precompute: xproj[s][g] = emb @ Wg_x + bg ---------------------
__global__ void __launch_bounds__(256)
precompute_kernel(const float* __restrict__ emb,
                  const float* __restrict__ Wz, const float* __restrict__ Wr,
                  const float* __restrict__ Wm,
                  const float* __restrict__ bz, const float* __restrict__ br,
                  const float* __restrict__ bm) {
    __shared__ float sA[128][36];
    __shared__ float sB[32][72];

    const int g = blockIdx.z;
    const float* __restrict__ W    = (g == 0) ? Wz : ((g == 1) ? Wr : Wm);
    const float* __restrict__ bias = (g == 0) ? bz : ((g == 1) ? br : bm);

    const int m0 = blockIdx.x * 128;
    const int j0 = blockIdx.y * 64;
    const int t = threadIdx.x;
    const int warp = t >> 5, lane = t & 31;
    const int wm = warp & 3, wn = warp >> 2;
    const int grp = lane >> 2, tg = lane & 3;

    float acc[2][4][4];
#pragma unroll
    for (int i = 0; i < 2; i++)
#pragma unroll
        for (int j = 0; j < 4; j++)
#pragma unroll
            for (int q = 0; q < 4; q++) acc[i][j][q] = 0.0f;

    for (int k0 = 0; k0 < INDIM; k0 += 32) {
#pragma unroll
        for (int i = 0; i < 4; i++) {
            int idx = t + i * 256;
            int r = idx >> 3, c4 = (idx & 7) * 4;
            float4 v = *(const float4*)(emb + (size_t)(m0 + r) * INDIM + k0 + c4);
            sA[r][c4 + 0] = to_tf32(v.x); sA[r][c4 + 1] = to_tf32(v.y);
            sA[r][c4 + 2] = to_tf32(v.z); sA[r][c4 + 3] = to_tf32(v.w);
        }
#pragma unroll
        for (int i = 0; i < 2; i++) {
            int idx = t + i * 256;
            int r = idx >> 4, c4 = (idx & 15) * 4;
            float4 v = *(const float4*)(W + (size_t)(k0 + r) * HID + j0 + c4);
            sB[r][c4 + 0] = to_tf32(v.x); sB[r][c4 + 1] = to_tf32(v.y);
            sB[r][c4 + 2] = to_tf32(v.z); sB[r][c4 + 3] = to_tf32(v.w);
        }
        __syncthreads();
#pragma unroll
        for (int kk = 0; kk < 4; kk++) {
            float a[2][4];
#pragma unroll
            for (int mt = 0; mt < 2; mt++) {
                int row = wm * 32 + mt * 16;
                int kc = kk * 8 + tg;
                a[mt][0] = sA[row + grp][kc];
                a[mt][1] = sA[row + grp + 8][kc];
                a[mt][2] = sA[row + grp][kc + 4];
                a[mt][3] = sA[row + grp + 8][kc + 4];
            }
            float b[4][2];
#pragma unroll
            for (int nt = 0; nt < 4; nt++) {
                int col = wn * 32 + nt * 8 + grp;
                b[nt][0] = sB[kk * 8 + tg][col];
                b[nt][1] = sB[kk * 8 + tg + 4][col];
            }
#pragma unroll
            for (int mt = 0; mt < 2; mt++)
#pragma unroll
                for (int nt = 0; nt < 4; nt++)
                    mma_tf32(acc[mt][nt], a[mt], b[nt]);
        }
        __syncthreads();
    }

#pragma unroll
    for (int mt = 0; mt < 2; mt++) {
#pragma unroll
        for (int nt = 0; nt < 4; nt++) {
            int r0 = m0 + wm * 32 + mt * 16 + grp;
            int c0 = j0 + wn * 32 + nt * 8 + tg * 2;
            float b0 = bias[c0], b1 = bias[c0 + 1];
            {
                int m = r0; int s = m >> 6, b = m & 63;
                float2 v = make_float2(acc[mt][nt][0] + b0, acc[mt][nt][1] + b1);
                *(float2*)&g_xproj[(((size_t)s * 3 + g) * BATCH + b) * HID + c0] = v;
            }
            {
                int m = r0 + 8; int s = m >> 6, b = m & 63;
                float2 v = make_float2(acc[mt][nt][2] + b0, acc[mt][nt][3] + b1);
                *(float2*)&g_xproj[(((size_t)s * 3 + g) * BATCH + b) * HID + c0] = v;
            }
        }
    }
}

// ---------------- persistent scan kernel ----------------------------------------
// SMEM (floats): sW1 1024x17 | sW2 1024x9 | sH 4x(64x68) | sC 64x17 | 4 mbarriers
#define SW1_ELEMS (1024 * 17)
#define SW2_ELEMS (1024 * 9)
#define SH_ELEMS  (4 * TILE_F)
#define SC_ELEMS  (64 * 17)
#define SMEM_FLOATS (SW1_ELEMS + SW2_ELEMS + SH_ELEMS + SC_ELEMS)
#define SMEM_BYTES  (SMEM_FLOATS * 4 + 64)

// wait for tile's producers, then one bulk copy of the padded k-tile (17408 B)
__device__ __forceinline__ void issue_tile(const float* __restrict__ src_t, float* dstbuf,
                                           int kt, const unsigned* cnt, unsigned tgt,
                                           unsigned mbar, int t) {
    if (t == 0) {
        while (ld_acq(&cnt[kt]) < tgt) {}
        mbar_expect_tx(mbar, TILE_B);
        bulk_cp(dstbuf, src_t + (size_t)kt * TILE_F, TILE_B, mbar);
    }
}

template <int PH>
__device__ __forceinline__ void gemm_phase(const float* __restrict__ src_t,
                                           const unsigned* cnt, unsigned tgt,
                                           const float* __restrict__ sW,
                                           float* __restrict__ sH, float* __restrict__ sC,
                                           unsigned mb0, unsigned mb1, unsigned mb2, unsigned mb3,
                                           unsigned& p0, unsigned& p1, unsigned& p2, unsigned& p3,
                                           int t, int wm, int wn, int grp, int tg) {
    float acc[4] = {0.f, 0.f, 0.f, 0.f};
    issue_tile(src_t, sH + 0 * TILE_F, 0, cnt, tgt, mb0, t);
    issue_tile(src_t, sH + 1 * TILE_F, 1, cnt, tgt, mb1, t);
    issue_tile(src_t, sH + 2 * TILE_F, 2, cnt, tgt, mb2, t);

#pragma unroll
    for (int kt = 0; kt < NTILE; kt++) {
        if (kt + 3 < NTILE) {
            const int nb = (kt + 3) & 3;
            unsigned mbn = (nb == 0) ? mb0 : (nb == 1) ? mb1 : (nb == 2) ? mb2 : mb3;
            issue_tile(src_t, sH + nb * TILE_F, kt + 3, cnt, tgt, mbn, t);
        }
        const int bc = kt & 3;
        unsigned mbc = (bc == 0) ? mb0 : (bc == 1) ? mb1 : (bc == 2) ? mb2 : mb3;
        unsigned par = (bc == 0) ? p0 : (bc == 1) ? p1 : (bc == 2) ? p2 : p3;
        mbar_wait(mbc, par);
        if (bc == 0) p0 ^= 1; else if (bc == 1) p1 ^= 1; else if (bc == 2) p2 ^= 1; else p3 ^= 1;

        const float* hb = sH + bc * TILE_F;
        if (PH == 1 || ((kt & 1) == wn)) {
#pragma unroll
            for (int kk = 0; kk < 8; kk++) {
                int kc = kk * 8 + tg;
                float a[4];
                a[0] = hb[(wm * 16 + grp) * 68 + kc];
                a[1] = hb[(wm * 16 + grp + 8) * 68 + kc];
                a[2] = hb[(wm * 16 + grp) * 68 + kc + 4];
                a[3] = hb[(wm * 16 + grp + 8) * 68 + kc + 4];
                int kg = kt * 64 + kk * 8;
                float b[2];
                if (PH == 1) {
                    b[0] = sW[(kg + tg) * 17 + wn * 8 + grp];
                    b[1] = sW[(kg + tg + 4) * 17 + wn * 8 + grp];
                } else {
                    b[0] = sW[(kg + tg) * 9 + grp];
                    b[1] = sW[(kg + tg + 4) * 9 + grp];
                }
                mma_tf32(acc, a, b);
            }
        }
        __syncthreads();
    }

    sC[(wm * 16 + grp) * 17 + wn * 8 + tg * 2]         = acc[0];
    sC[(wm * 16 + grp) * 17 + wn * 8 + tg * 2 + 1]     = acc[1];
    sC[(wm * 16 + grp + 8) * 17 + wn * 8 + tg * 2]     = acc[2];
    sC[(wm * 16 + grp + 8) * 17 + wn * 8 + tg * 2 + 1] = acc[3];
    __syncthreads();
}

__global__ void __launch_bounds__(256, 1)
scan_kernel(const float* __restrict__ Wz, const float* __restrict__ Wr,
            const float* __restrict__ Wm, float* __restrict__ out) {
    extern __shared__ float smem[];
    float* sW1 = smem;
    float* sW2 = sW1 + SW1_ELEMS;
    float* sH  = sW2 + SW2_ELEMS;
    float* sC  = sH + SH_ELEMS;
    unsigned long long* mbars = (unsigned long long*)(sC + SC_ELEMS);

    const int c = blockIdx.x;
    const int t = threadIdx.x;
    const int warp = t >> 5, lane = t & 31;
    const int grp = lane >> 2, tg = lane & 3;
    const int wm = warp & 3;
    const int wn = warp >> 2;

    const int col0 = (c & 63) * 16;   // phase-1 column base within its gate
    const int colm = c * 8;           // phase-2 column base

    const unsigned mb0 = (unsigned)__cvta_generic_to_shared(&mbars[0]);
    const unsigned mb1 = (unsigned)__cvta_generic_to_shared(&mbars[1]);
    const unsigned mb2 = (unsigned)__cvta_generic_to_shared(&mbars[2]);
    const unsigned mb3 = (unsigned)__cvta_generic_to_shared(&mbars[3]);
    if (t == 0) { mbar_init(mb0, 1); mbar_init(mb1, 1); mbar_init(mb2, 1); mbar_init(mb3, 1); }
    asm volatile("fence.proxy.async.shared::cta;" ::: "memory");

    // ---- load weight slices into SMEM (tf32) ----
    {
        const float* Wzr = (c < 64) ? Wz : Wr;
        for (int i = t; i < 1024 * 4; i += 256) {
            int k = i >> 2, q = (i & 3) * 4;
            float4 v = *(const float4*)(Wzr + (size_t)(512 + k) * HID + col0 + q);
            float* d = sW1 + k * 17 + q;
            d[0] = to_tf32(v.x); d[1] = to_tf32(v.y);
            d[2] = to_tf32(v.z); d[3] = to_tf32(v.w);
        }
        for (int i = t; i < 1024 * 2; i += 256) {
            int k = i >> 1, q = (i & 1) * 4;
            float4 v = *(const float4*)(Wm + (size_t)(512 + k) * HID + colm + q);
            float* d = sW2 + k * 9 + q;
            d[0] = to_tf32(v.x); d[1] = to_tf32(v.y);
            d[2] = to_tf32(v.z); d[3] = to_tf32(v.w);
        }
    }
    __syncthreads();

    unsigned p0 = 0, p1 = 0, p2 = 0, p3 = 0;

    for (int s = 0; s < SEQ; s++) {
        // =================== PHASE 1: z,r gates ===================
        const float* htb = g_ht_t + (size_t)(s & 1) * HT_BUF_F;
        gemm_phase<1>(htb, g_cnt_ht, 8u * (unsigned)s, sW1, sH, sC,
                      mb0, mb1, mb2, mb3, p0, p1, p2, p3, t, wm, wn, grp, tg);
        {
            const float* xg = g_xproj + ((size_t)s * 3 + (c < 64 ? 0 : 1)) * BATCH * HID;
            const int tile = col0 >> 6, cw = col0 & 63;
#pragma unroll
            for (int i = 0; i < 4; i++) {
                int idx = t + i * 256;
                int b = idx >> 4, j = idx & 15;
                float val = xg[(size_t)b * HID + col0 + j] + sC[b * 17 + j];
                if (c < 64) {
                    __stcg(&g_z[b * HID + col0 + j], sigmoidf_(val));
                } else {
                    float r = sigmoidf_(val);
                    float h = __ldcg(&g_h[b * HID + col0 + j]);
                    __stcg(&g_rh_t[(size_t)tile * TILE_F + b * 68 + cw + j], to_tf32(r * h));
                }
            }
            __syncthreads();
            if (t == 0) {
                if (c < 64) st_rel(&g_flag_z[c], (unsigned)(s + 1));
                else        red_rel(&g_cnt_rh[col0 >> 6], 1u);
            }
        }

        // =================== PHASE 2: m gate + h update ===================
        gemm_phase<2>(g_rh_t, g_cnt_rh, 4u * (unsigned)(s + 1), sW2, sH, sC,
                      mb0, mb1, mb2, mb3, p0, p1, p2, p3, t, wm, wn, grp, tg);
        {
            if (t == 0) {
                while (ld_acq(&g_flag_z[c >> 1]) < (unsigned)(s + 1)) {}
            }
            __syncthreads();
            float* htw = g_ht_t + (size_t)((s + 1) & 1) * HT_BUF_F;
            const int tile = colm >> 6, cw = colm & 63;
#pragma unroll
            for (int i = 0; i < 2; i++) {
                int idx = t + i * 256;
                int b = idx >> 3, j = idx & 7;
                float cm = sC[b * 17 + j] + sC[b * 17 + 8 + j];
                float xm = g_xproj[(((size_t)s * 3 + 2) * BATCH + b) * HID + colm + j];
                float ht = tanhf(xm + cm);
                float z = __ldcg(&g_z[b * HID + colm + j]);
                float h = __ldcg(&g_h[b * HID + colm + j]);
                float hn = (1.0f - z) * h + z * ht;
                __stcg(&g_h[b * HID + colm + j], hn);
                __stcg(&htw[(size_t)tile * TILE_F + b * 68 + cw + j], to_tf32(hn));
                __stcg(&out[((size_t)b * SEQ + s) * HID + colm + j], hn);
            }
            __syncthreads();
            if (t == 0) red_rel(&g_cnt_ht[c >> 3], 1u);
        }
    }
}

// ---------------- launch ---------------------------------------------------------
extern "C" void kernel_launch(void* const* d_in, const int* in_sizes, int n_in,
                              void* d_out, int out_size) {
    const float* emb    = (const float*)d_in[0];
    const float* init_h = (const float*)d_in[1];
    const float* Wz     = (const float*)d_in[2];
    const float* bz     = (const float*)d_in[3];
    const float* Wr     = (const float*)d_in[4];
    const float* br     = (const float*)d_in[5];
    const float* Wm     = (const float*)d_in[6];
    const float* bm     = (const float*)d_in[7];
    float* out = (float*)d_out;

    static bool attr_done = false;
    if (!attr_done) {
        cudaFuncSetAttribute(scan_kernel, cudaFuncAttributeMaxDynamicSharedMemorySize,
                             SMEM_BYTES);
        attr_done = true;
    }

    init_kernel<<<(BATCH * HID + 255) / 256, 256>>>(init_h);

    dim3 pg((SEQ * BATCH) / 128, HID / 64, 3);
    precompute_kernel<<<pg, 256>>>(emb, Wz, Wr, Wm, bz, br, bm);

    scan_kernel<<<NCTA, 256, SMEM_BYTES>>>(Wz, Wr, Wm, out);
}

// round 7
// speedup vs baseline: 1.2910x; 1.2910x over previous
#include <cuda_runtime.h>
#include <cstdint>
#include <cstddef>

#define SEQ   512
#define BATCH 64
#define INDIM 512
#define HID   1024
#define NCTA  128

#define TILE_F   (64 * 68)          // floats per padded k-tile (64 rows x 68)
#define TILE_B   (TILE_F * 4)       // 17408 bytes
#define NTILE    16                 // 16 k-tiles of 64 cover K=1024

// ---------------- device scratch ----------------
__device__ float g_xproj[(size_t)SEQ * 3 * BATCH * HID];   // [s][gate][b][j]
__device__ float g_h[BATCH * HID];            // exact fp32 hidden (linear)
__device__ float g_ht_t[NTILE * TILE_F];      // tf32 hidden, tiled+padded [tile][b][68]
__device__ float g_rh_t[NTILE * TILE_F];      // tf32 r*h,  tiled+padded
__device__ float g_z[BATCH * HID];
__device__ unsigned g_count;

// ---------------- helpers ----------------
__device__ __forceinline__ float to_tf32(float x) {
    uint32_t u;
    asm("cvt.rna.tf32.f32 %0, %1;" : "=r"(u) : "f"(x));
    return __uint_as_float(u);
}

__device__ __forceinline__ void mma_tf32(float c[4], const float a[4], const float b[2]) {
    asm volatile(
        "mma.sync.aligned.m16n8k8.row.col.f32.tf32.tf32.f32 "
        "{%0,%1,%2,%3}, {%4,%5,%6,%7}, {%8,%9}, {%0,%1,%2,%3};\n"
        : "+f"(c[0]), "+f"(c[1]), "+f"(c[2]), "+f"(c[3])
        : "r"(__float_as_uint(a[0])), "r"(__float_as_uint(a[1])),
          "r"(__float_as_uint(a[2])), "r"(__float_as_uint(a[3])),
          "r"(__float_as_uint(b[0])), "r"(__float_as_uint(b[1])));
}

__device__ __forceinline__ float sigmoidf_(float x) {
    return 1.0f / (1.0f + __expf(-x));
}

__device__ __forceinline__ void mbar_init(unsigned addr, unsigned cnt) {
    asm volatile("mbarrier.init.shared.b64 [%0], %1;" :: "r"(addr), "r"(cnt) : "memory");
}
__device__ __forceinline__ void mbar_expect_tx(unsigned addr, unsigned tx) {
    asm volatile("mbarrier.arrive.expect_tx.shared.b64 _, [%0], %1;"
                 :: "r"(addr), "r"(tx) : "memory");
}
__device__ __forceinline__ void mbar_arrive(unsigned addr) {
    asm volatile("mbarrier.arrive.shared.b64 _, [%0];" :: "r"(addr) : "memory");
}
__device__ __forceinline__ void mbar_wait(unsigned addr, unsigned parity) {
    asm volatile(
        "{\n\t.reg .pred P;\n\t"
        "LW%=:\n\t"
        "mbarrier.try_wait.parity.shared.b64 P, [%0], %1;\n\t"
        "@P bra.uni LD%=;\n\t"
        "bra.uni LW%=;\n\t"
        "LD%=:\n\t}"
        :: "r"(addr), "r"(parity) : "memory");
}
__device__ __forceinline__ void bulk_cp(float* dst_smem, const float* src,
                                        unsigned bytes, unsigned mbar) {
    unsigned d = (unsigned)__cvta_generic_to_shared(dst_smem);
    asm volatile(
        "cp.async.bulk.shared::cta.global.mbarrier::complete_tx::bytes [%0], [%1], %2, [%3];"
        :: "r"(d), "l"(src), "r"(bytes), "r"(mbar) : "memory");
}

__device__ __forceinline__ void grid_barrier(unsigned epoch) {
    __syncthreads();
    if (threadIdx.x == 0) {
        __threadfence();
        atomicAdd(&g_count, 1u);
        unsigned target = epoch * NCTA;
        while (__ldcg(&g_count) < target) { __nanosleep(32); }
    }
    __syncthreads();
}

// ---------------- init: h (linear + tiled tf32), barrier counter ----------------
__global__ void init_kernel(const float* __restrict__ init_h) {
    int i = blockIdx.x * blockDim.x + threadIdx.x;
    if (i == 0) g_count = 0u;
    if (i < BATCH * HID) {
        int b = i >> 10, j = i & 1023;
        float v = init_h[i];
        g_h[i] = v;
        g_ht_t[(j >> 6) * TILE_F + b * 68 + (j & 63)] = to_tf32(v);
    }
}

// ---------------- precompute: xproj[s][g] = emb @ Wg_x + bg ---------------------
__global__ void __launch_bounds__(256)
precompute_kernel(const float* __restrict__ emb,
                  const float* __restrict__ Wz, const float* __restrict__ Wr,
                  const float* __restrict__ Wm,
                  const float* __restrict__ bz, const float* __restrict__ br,
                  const float* __restrict__ bm) {
    __shared__ float sA[128][36];
    __shared__ float sB[32][72];

    const int g = blockIdx.z;
    const float* __restrict__ W    = (g == 0) ? Wz : ((g == 1) ? Wr : Wm);
    const float* __restrict__ bias = (g == 0) ? bz : ((g == 1) ? br : bm);

    const int m0 = blockIdx.x * 128;
    const int j0 = blockIdx.y * 64;
    const int t = threadIdx.x;
    const int warp = t >> 5, lane = t & 31;
    const int wm = warp & 3, wn = warp >> 2;
    const int grp = lane >> 2, tg = lane & 3;

    float acc[2][4][4];
#pragma unroll
    for (int i = 0; i < 2; i++)
#pragma unroll
        for (int j = 0; j < 4; j++)
#pragma unroll
            for (int q = 0; q < 4; q++) acc[i][j][q] = 0.0f;

    for (int k0 = 0; k0 < INDIM; k0 += 32) {
#pragma unroll
        for (int i = 0; i < 4; i++) {
            int idx = t + i * 256;
            int r = idx >> 3, c4 = (idx & 7) * 4;
            float4 v = *(const float4*)(emb + (size_t)(m0 + r) * INDIM + k0 + c4);
            sA[r][c4 + 0] = to_tf32(v.x); sA[r][c4 + 1] = to_tf32(v.y);
            sA[r][c4 + 2] = to_tf32(v.z); sA[r][c4 + 3] = to_tf32(v.w);
        }
#pragma unroll
        for (int i = 0; i < 2; i++) {
            int idx = t + i * 256;
            int r = idx >> 4, c4 = (idx & 15) * 4;
            float4 v = *(const float4*)(W + (size_t)(k0 + r) * HID + j0 + c4);
            sB[r][c4 + 0] = to_tf32(v.x); sB[r][c4 + 1] = to_tf32(v.y);
            sB[r][c4 + 2] = to_tf32(v.z); sB[r][c4 + 3] = to_tf32(v.w);
        }
        __syncthreads();
#pragma unroll
        for (int kk = 0; kk < 4; kk++) {
            float a[2][4];
#pragma unroll
            for (int mt = 0; mt < 2; mt++) {
                int row = wm * 32 + mt * 16;
                int kc = kk * 8 + tg;
                a[mt][0] = sA[row + grp][kc];
                a[mt][1] = sA[row + grp + 8][kc];
                a[mt][2] = sA[row + grp][kc + 4];
                a[mt][3] = sA[row + grp + 8][kc + 4];
            }
            float b[4][2];
#pragma unroll
            for (int nt = 0; nt < 4; nt++) {
                int col = wn * 32 + nt * 8 + grp;
                b[nt][0] = sB[kk * 8 + tg][col];
                b[nt][1] = sB[kk * 8 + tg + 4][col];
            }
#pragma unroll
            for (int mt = 0; mt < 2; mt++)
#pragma unroll
                for (int nt = 0; nt < 4; nt++)
                    mma_tf32(acc[mt][nt], a[mt], b[nt]);
        }
        __syncthreads();
    }

#pragma unroll
    for (int mt = 0; mt < 2; mt++) {
#pragma unroll
        for (int nt = 0; nt < 4; nt++) {
            int r0 = m0 + wm * 32 + mt * 16 + grp;
            int c0 = j0 + wn * 32 + nt * 8 + tg * 2;
            float b0 = bias[c0], b1 = bias[c0 + 1];
            {
                int m = r0; int s = m >> 6, b = m & 63;
                float2 v = make_float2(acc[mt][nt][0] + b0, acc[mt][nt][1] + b1);
                *(float2*)&g_xproj[(((size_t)s * 3 + g) * BATCH + b) * HID + c0] = v;
            }
            {
                int m = r0 + 8; int s = m >> 6, b = m & 63;
                float2 v = make_float2(acc[mt][nt][2] + b0, acc[mt][nt][3] + b1);
                *(float2*)&g_xproj[(((size_t)s * 3 + g) * BATCH + b) * HID + c0] = v;
            }
        }
    }
}

// ---------------- persistent scan kernel ----------------------------------------
// SMEM (floats): sW1 1024x17 | sW2 1024x9 | sH 4x(64x68) | sC 64x33 | 8 mbarriers
#define SW1_ELEMS (1024 * 17)
#define SW2_ELEMS (1024 * 9)
#define SH_ELEMS  (4 * TILE_F)
#define SC_ELEMS  (64 * 33)
#define SMEM_FLOATS (SW1_ELEMS + SW2_ELEMS + SH_ELEMS + SC_ELEMS)
#define SMEM_BYTES  (SMEM_FLOATS * 4 + 128)

// Both phases: warps split even/odd k-tiles (wn = parity). Phase1 computes 2
// n-blocks per warp (16 cols), phase2 one n-block (8 cols). Halves reduced via sC.
template <int PH>
__device__ __forceinline__ void gemm_phase(const float* __restrict__ src_t,
                                           const float* __restrict__ sW,
                                           float* __restrict__ sH, float* __restrict__ sC,
                                           unsigned mbase,
                                           unsigned (&pf)[4], unsigned (&pe)[4],
                                           int t, int lane, int wm, int wn, int grp, int tg) {
    float acc0[4] = {0.f, 0.f, 0.f, 0.f};
    float acc1[4] = {0.f, 0.f, 0.f, 0.f};

    // prefetch stages 0..2 (first-ever empty waits pass immediately via parity=1)
#pragma unroll
    for (int i = 0; i < 3; i++) {
        if (t == 0) {
            mbar_wait(mbase + 32 + i * 8, pe[i]);
            mbar_expect_tx(mbase + i * 8, TILE_B);
            bulk_cp(sH + i * TILE_F, src_t + (size_t)i * TILE_F, TILE_B, mbase + i * 8);
        }
        if (t == 0) pe[i] ^= 1u;
    }

#pragma unroll
    for (int kt = 0; kt < NTILE; kt++) {
        const int bc = kt & 3;
        // consumer: wait full
        mbar_wait(mbase + bc * 8, pf[bc]);
        pf[bc] ^= 1u;

        const float* hb = sH + bc * TILE_F;
        if ((kt & 1) == wn) {
#pragma unroll
            for (int kk = 0; kk < 8; kk++) {
                int kc = kk * 8 + tg;
                float a[4];
                a[0] = hb[(wm * 16 + grp) * 68 + kc];
                a[1] = hb[(wm * 16 + grp + 8) * 68 + kc];
                a[2] = hb[(wm * 16 + grp) * 68 + kc + 4];
                a[3] = hb[(wm * 16 + grp + 8) * 68 + kc + 4];
                int kg = kt * 64 + kk * 8;
                float b0[2];
                if (PH == 1) {
                    b0[0] = sW[(kg + tg) * 17 + grp];
                    b0[1] = sW[(kg + tg + 4) * 17 + grp];
                    float b1[2];
                    b1[0] = sW[(kg + tg) * 17 + 8 + grp];
                    b1[1] = sW[(kg + tg + 4) * 17 + 8 + grp];
                    mma_tf32(acc0, a, b0);
                    mma_tf32(acc1, a, b1);
                } else {
                    b0[0] = sW[(kg + tg) * 9 + grp];
                    b0[1] = sW[(kg + tg + 4) * 9 + grp];
                    mma_tf32(acc0, a, b0);
                }
            }
        }
        // consumer release
        if (lane == 0) mbar_arrive(mbase + 32 + bc * 8);

        // producer: issue tile kt+3 into the stage just released (lag-4 ring)
        if (kt + 3 < NTILE) {
            const int nb = (kt + 3) & 3;
            if (t == 0) {
                mbar_wait(mbase + 32 + nb * 8, pe[nb]);
                mbar_expect_tx(mbase + nb * 8, TILE_B);
                bulk_cp(sH + nb * TILE_F, src_t + (size_t)(kt + 3) * TILE_F,
                        TILE_B, mbase + nb * 8);
            }
            if (t == 0) pe[nb] ^= 1u;
        }
    }

    // stage accumulators: halves at column offsets {0,16} (PH1) / {0,8} (PH2)
    if (PH == 1) {
        int r = wm * 16 + grp;
        int cb = wn * 16;
        sC[r * 33 + cb + tg * 2]          = acc0[0];
        sC[r * 33 + cb + tg * 2 + 1]      = acc0[1];
        sC[(r + 8) * 33 + cb + tg * 2]    = acc0[2];
        sC[(r + 8) * 33 + cb + tg * 2 + 1] = acc0[3];
        sC[r * 33 + cb + 8 + tg * 2]          = acc1[0];
        sC[r * 33 + cb + 8 + tg * 2 + 1]      = acc1[1];
        sC[(r + 8) * 33 + cb + 8 + tg * 2]    = acc1[2];
        sC[(r + 8) * 33 + cb + 8 + tg * 2 + 1] = acc1[3];
    } else {
        int r = wm * 16 + grp;
        int cb = wn * 8;
        sC[r * 33 + cb + tg * 2]           = acc0[0];
        sC[r * 33 + cb + tg * 2 + 1]       = acc0[1];
        sC[(r + 8) * 33 + cb + tg * 2]     = acc0[2];
        sC[(r + 8) * 33 + cb + tg * 2 + 1] = acc0[3];
    }
    __syncthreads();
}

__global__ void __launch_bounds__(256, 1)
scan_kernel(const float* __restrict__ Wz, const float* __restrict__ Wr,
            const float* __restrict__ Wm, float* __restrict__ out) {
    extern __shared__ float smem[];
    float* sW1 = smem;
    float* sW2 = sW1 + SW1_ELEMS;
    float* sH  = sW2 + SW2_ELEMS;
    float* sC  = sH + SH_ELEMS;
    unsigned long long* mbars = (unsigned long long*)(sC + SC_ELEMS);

    const int c = blockIdx.x;
    const int t = threadIdx.x;
    const int warp = t >> 5, lane = t & 31;
    const int grp = lane >> 2, tg = lane & 3;
    const int wm = warp & 3;
    const int wn = warp >> 2;     // k-parity split

    const int col0 = (c & 63) * 16;   // phase-1 column base within its gate
    const int colm = c * 8;           // phase-2 column base

    // mbarrier region: full[0..3] at mbase+0..24, empty[0..3] at mbase+32..56
    const unsigned mbase = (unsigned)__cvta_generic_to_shared(mbars);
    if (t == 0) {
#pragma unroll
        for (int i = 0; i < 4; i++) {
            mbar_init(mbase + i * 8, 1);        // full: 1 arrival (expect_tx)
            mbar_init(mbase + 32 + i * 8, 8);   // empty: 8 warp arrivals
        }
    }
    asm volatile("fence.proxy.async.shared::cta;" ::: "memory");

    // ---- load weight slices into SMEM (tf32) ----
    {
        const float* Wzr = (c < 64) ? Wz : Wr;
        for (int i = t; i < 1024 * 4; i += 256) {
            int k = i >> 2, q = (i & 3) * 4;
            float4 v = *(const float4*)(Wzr + (size_t)(512 + k) * HID + col0 + q);
            float* d = sW1 + k * 17 + q;
            d[0] = to_tf32(v.x); d[1] = to_tf32(v.y);
            d[2] = to_tf32(v.z); d[3] = to_tf32(v.w);
        }
        for (int i = t; i < 1024 * 2; i += 256) {
            int k = i >> 1, q = (i & 1) * 4;
            float4 v = *(const float4*)(Wm + (size_t)(512 + k) * HID + colm + q);
            float* d = sW2 + k * 9 + q;
            d[0] = to_tf32(v.x); d[1] = to_tf32(v.y);
            d[2] = to_tf32(v.z); d[3] = to_tf32(v.w);
        }
    }
    __syncthreads();

    unsigned epoch = 0;
    unsigned pf[4] = {0u, 0u, 0u, 0u};   // full parities (consumer)
    unsigned pe[4] = {1u, 1u, 1u, 1u};   // empty parities (producer; first wait passes)

    for (int s = 0; s < SEQ; s++) {
        // =================== PHASE 1: z,r gates ===================
        gemm_phase<1>(g_ht_t, sW1, sH, sC, mbase, pf, pe, t, lane, wm, wn, grp, tg);
        {
            const float* xg = g_xproj + ((size_t)s * 3 + (c < 64 ? 0 : 1)) * BATCH * HID;
            const int tile = col0 >> 6, cw = col0 & 63;
#pragma unroll
            for (int i = 0; i < 4; i++) {
                int idx = t + i * 256;
                int b = idx >> 4, j = idx & 15;
                float val = xg[(size_t)b * HID + col0 + j] + sC[b * 33 + j] + sC[b * 33 + 16 + j];
                if (c < 64) {
                    __stcg(&g_z[b * HID + col0 + j], sigmoidf_(val));
                } else {
                    float r = sigmoidf_(val);
                    float h = __ldcg(&g_h[b * HID + col0 + j]);
                    __stcg(&g_rh_t[(size_t)tile * TILE_F + b * 68 + cw + j], to_tf32(r * h));
                }
            }
        }
        grid_barrier(++epoch);

        // =================== PHASE 2: m gate + h update ===================
        gemm_phase<2>(g_rh_t, sW2, sH, sC, mbase, pf, pe, t, lane, wm, wn, grp, tg);
        {
            const int tile = colm >> 6, cw = colm & 63;
#pragma unroll
            for (int i = 0; i < 2; i++) {
                int idx = t + i * 256;
                int b = idx >> 3, j = idx & 7;
                float cm = sC[b * 33 + j] + sC[b * 33 + 8 + j];
                float xm = g_xproj[(((size_t)s * 3 + 2) * BATCH + b) * HID + colm + j];
                float ht = tanhf(xm + cm);
                float z = __ldcg(&g_z[b * HID + colm + j]);
                float h = __ldcg(&g_h[b * HID + colm + j]);
                float hn = (1.0f - z) * h + z * ht;
                __stcg(&g_h[b * HID + colm + j], hn);
                __stcg(&g_ht_t[(size_t)tile * TILE_F + b * 68 + cw + j], to_tf32(hn));
                __stcg(&out[((size_t)b * SEQ + s) * HID + colm + j], hn);
            }
        }
        grid_barrier(++epoch);
    }
}

// ---------------- launch ---------------------------------------------------------
extern "C" void kernel_launch(void* const* d_in, const int* in_sizes, int n_in,
                              void* d_out, int out_size) {
    const float* emb    = (const float*)d_in[0];
    const float* init_h = (const float*)d_in[1];
    const float* Wz     = (const float*)d_in[2];
    const float* bz     = (const float*)d_in[3];
    const float* Wr     = (const float*)d_in[4];
    const float* br     = (const float*)d_in[5];
    const float* Wm     = (const float*)d_in[6];
    const float* bm     = (const float*)d_in[7];
    float* out = (float*)d_out;

    static bool attr_done = false;
    if (!attr_done) {
        cudaFuncSetAttribute(scan_kernel, cudaFuncAttributeMaxDynamicSharedMemorySize,
                             SMEM_BYTES);
        attr_done = true;
    }

    init_kernel<<<(BATCH * HID + 255) / 256, 256>>>(init_h);

    dim3 pg((SEQ * BATCH) / 128, HID / 64, 3);
    precompute_kernel<<<pg, 256>>>(emb, Wz, Wr, Wm, bz, br, bm);

    scan_kernel<<<NCTA, 256, SMEM_BYTES>>>(Wz, Wr, Wm, out);
}